// round 3
// baseline (speedup 1.0000x reference)
#include <cuda_runtime.h>
#include <math.h>
#include <stdint.h>

#define BATCH 2
#define SEQ   4096
#define DMODEL 256
#define NHEAD 8
#define DHEAD 32
#define DMLP  1024
#define NROW  (BATCH*SEQ)   // 8192

// ---------------- scratch (static device globals; no allocation) -------------
__device__ float g_xn[NROW*DMODEL];
__device__ float g_qkv[NROW*3*DMODEL];
__device__ float g_attn[NROW*DMODEL];
__device__ float g_mlpin[NROW*DMODEL];
__device__ float g_yn[NROW*DMODEL];
__device__ float g_h[NROW*DMLP];

// inv_freq[i] = 10000^(-i/16) = 10^(-i/4), double-accurate literals
__constant__ float c_invfreq[16] = {
    1.0f, 0.5623413251903491f, 0.31622776601683794f, 0.17782794100389228f,
    0.1f, 0.05623413251903491f, 0.031622776601683794f, 0.017782794100389228f,
    0.01f, 0.005623413251903491f, 0.0031622776601683794f, 0.0017782794100389228f,
    0.001f, 0.0005623413251903491f, 0.00031622776601683794f, 0.00017782794100389227f
};

// ---------------- LayerNorm: one block per row, 256 threads ------------------
__global__ void ln_kernel(const float* __restrict__ x, const float* __restrict__ g,
                          const float* __restrict__ b, float* __restrict__ out)
{
    const int row = blockIdx.x;
    const int t   = threadIdx.x;
    const float v = x[row*DMODEL + t];
    __shared__ float red1[8];
    __shared__ float red2[8];

    float s = v;
    #pragma unroll
    for (int o = 16; o > 0; o >>= 1) s += __shfl_xor_sync(0xffffffffu, s, o);
    if ((t & 31) == 0) red1[t >> 5] = s;
    __syncthreads();
    float mean = 0.f;
    #pragma unroll
    for (int i = 0; i < 8; i++) mean += red1[i];
    mean *= (1.0f/DMODEL);
    const float d = v - mean;

    float s2 = d*d;
    #pragma unroll
    for (int o = 16; o > 0; o >>= 1) s2 += __shfl_xor_sync(0xffffffffu, s2, o);
    if ((t & 31) == 0) red2[t >> 5] = s2;
    __syncthreads();
    float var = 0.f;
    #pragma unroll
    for (int i = 0; i < 8; i++) var += red2[i];
    var *= (1.0f/DMODEL);

    out[row*DMODEL + t] = d * rsqrtf(var + 1e-5f) * g[t] + b[t];
}

// ---------------- GEMM (C = A * B^T), NT, fp32 -------------------------------
// A: [M,K] row-major (lda), B: [N,K] row-major (ldb), C: [M,N] (ldc)
// Tiles: 128x128x16, 256 threads, 8x8 per thread (two 4x4 quadrant pairs).
enum { EPI_NONE=0, EPI_ROPE=1, EPI_BIAS_GELU=2, EPI_RESID=3, EPI_BIAS_RESID=4 };

template<int EPI>
__global__ __launch_bounds__(256, 2)
void gemm_nt(const float* __restrict__ A, int lda,
             const float* __restrict__ Bw, int ldb,
             float* __restrict__ C, int ldc,
             int K,
             const float* __restrict__ bias,
             const float* __restrict__ resid, int ldr)
{
    __shared__ float As[16][132];
    __shared__ float Bs[16][132];

    const int tid = threadIdx.x;
    const int m0 = blockIdx.y * 128;
    const int n0 = blockIdx.x * 128;

    const int lm = tid >> 1;            // 0..127
    const int lk = (tid & 1) * 8;       // 0 or 8
    const float* Ap = A  + (size_t)(m0 + lm) * lda + lk;
    const float* Bp = Bw + (size_t)(n0 + lm) * ldb + lk;

    float acc[8][8];
    #pragma unroll
    for (int i = 0; i < 8; i++)
        #pragma unroll
        for (int j = 0; j < 8; j++) acc[i][j] = 0.f;

    const int rb = (tid >> 4) * 4;      // 0..60
    const int cb = (tid & 15) * 4;      // 0..60

    for (int k0 = 0; k0 < K; k0 += 16) {
        float4 a0 = *(const float4*)(Ap + k0);
        float4 a1 = *(const float4*)(Ap + k0 + 4);
        float4 b0 = *(const float4*)(Bp + k0);
        float4 b1 = *(const float4*)(Bp + k0 + 4);
        __syncthreads();
        As[lk+0][lm]=a0.x; As[lk+1][lm]=a0.y; As[lk+2][lm]=a0.z; As[lk+3][lm]=a0.w;
        As[lk+4][lm]=a1.x; As[lk+5][lm]=a1.y; As[lk+6][lm]=a1.z; As[lk+7][lm]=a1.w;
        Bs[lk+0][lm]=b0.x; Bs[lk+1][lm]=b0.y; Bs[lk+2][lm]=b0.z; Bs[lk+3][lm]=b0.w;
        Bs[lk+4][lm]=b1.x; Bs[lk+5][lm]=b1.y; Bs[lk+6][lm]=b1.z; Bs[lk+7][lm]=b1.w;
        __syncthreads();

        #pragma unroll
        for (int kk = 0; kk < 16; kk++) {
            float4 av0 = *(const float4*)&As[kk][rb];
            float4 av1 = *(const float4*)&As[kk][rb + 64];
            float4 bv0 = *(const float4*)&Bs[kk][cb];
            float4 bv1 = *(const float4*)&Bs[kk][cb + 64];
            float a[8] = {av0.x,av0.y,av0.z,av0.w, av1.x,av1.y,av1.z,av1.w};
            float b[8] = {bv0.x,bv0.y,bv0.z,bv0.w, bv1.x,bv1.y,bv1.z,bv1.w};
            #pragma unroll
            for (int i = 0; i < 8; i++)
                #pragma unroll
                for (int j = 0; j < 8; j++)
                    acc[i][j] += a[i] * b[j];
        }
    }

    // epilogue + store
    #pragma unroll
    for (int ih = 0; ih < 2; ih++) {
        #pragma unroll
        for (int i = 0; i < 4; i++) {
            const int gm = m0 + ih*64 + rb + i;
            const int ri = ih*4 + i;
            #pragma unroll
            for (int jh = 0; jh < 2; jh++) {
                const int gc = n0 + jh*64 + cb;   // multiple of 4
                float v[4];
                #pragma unroll
                for (int j = 0; j < 4; j++) v[j] = acc[ri][jh*4 + j];

                if (EPI == EPI_ROPE) {
                    const int s  = gm & (SEQ - 1);
                    const int dd = gc & (DHEAD - 1);   // multiple of 4
                    #pragma unroll
                    for (int p = 0; p < 2; p++) {
                        const float ang = (float)s * c_invfreq[(dd >> 1) + p];
                        float sn, cs;
                        sincosf(ang, &sn, &cs);
                        const float e = v[2*p], o = v[2*p + 1];
                        v[2*p]     = e*cs - o*sn;
                        v[2*p + 1] = o*cs + e*sn;
                    }
                } else if (EPI == EPI_BIAS_GELU) {
                    #pragma unroll
                    for (int j = 0; j < 4; j++) {
                        const float t = v[j] + bias[gc + j];
                        v[j] = 0.5f * t * (1.0f + erff(t * 0.7071067811865476f));
                    }
                } else if (EPI == EPI_RESID) {
                    #pragma unroll
                    for (int j = 0; j < 4; j++)
                        v[j] += resid[(size_t)gm * ldr + gc + j];
                } else if (EPI == EPI_BIAS_RESID) {
                    #pragma unroll
                    for (int j = 0; j < 4; j++)
                        v[j] += bias[gc + j] + resid[(size_t)gm * ldr + gc + j];
                }

                *(float4*)&C[(size_t)gm * ldc + gc] = make_float4(v[0], v[1], v[2], v[3]);
            }
        }
    }
}

// ---------------- Flash attention, fp32, 64x64 tiles, DH=32 ------------------
__global__ __launch_bounds__(256)
void flash_attn(const float* __restrict__ qkv, float* __restrict__ out)
{
    __shared__ float Qs[64][33];
    __shared__ float Ks[64][33];
    __shared__ float Vs[64][33];
    __shared__ float Ps[64][68];

    const int tid = threadIdx.x;
    const int bh  = blockIdx.y;
    const int b   = bh >> 3;
    const int h   = bh & 7;
    const int qbase = blockIdx.x * 64;

    // load Q tile [64 x 32]
    for (int e = tid; e < 64*32; e += 256) {
        const int r = e >> 5, d = e & 31;
        Qs[r][d] = qkv[(size_t)(b*SEQ + qbase + r) * 768 + h*32 + d];
    }

    const int r0 = (tid >> 4) * 4;   // rows owned (S & P & O)
    const int c0 = (tid & 15) * 4;   // S cols owned
    const int d0 = (tid & 15) * 2;   // O dims owned

    float m[4], l[4], acc0[4], acc1[4];
    #pragma unroll
    for (int i = 0; i < 4; i++) { m[i] = -1e30f; l[i] = 0.f; acc0[i] = 0.f; acc1[i] = 0.f; }

    const float scale = 0.17677669529663687f;  // 1/sqrt(32)

    for (int kt = 0; kt < SEQ/64; kt++) {
        __syncthreads();  // prev PV done (and first-iter: Q load visible)
        const int kbase = kt * 64;
        for (int e = tid; e < 64*32; e += 256) {
            const int r = e >> 5, d = e & 31;
            const size_t gidx = (size_t)(b*SEQ + kbase + r) * 768 + h*32 + d;
            Ks[r][d] = qkv[gidx + 256];
            Vs[r][d] = qkv[gidx + 512];
        }
        __syncthreads();

        // S = Q K^T (4x4 per thread)
        float sacc[4][4];
        #pragma unroll
        for (int i = 0; i < 4; i++)
            #pragma unroll
            for (int j = 0; j < 4; j++) sacc[i][j] = 0.f;

        #pragma unroll
        for (int kk = 0; kk < 32; kk++) {
            const float a0 = Qs[r0+0][kk], a1 = Qs[r0+1][kk];
            const float a2 = Qs[r0+2][kk], a3 = Qs[r0+3][kk];
            const float k0v = Ks[c0+0][kk], k1v = Ks[c0+1][kk];
            const float k2v = Ks[c0+2][kk], k3v = Ks[c0+3][kk];
            sacc[0][0]+=a0*k0v; sacc[0][1]+=a0*k1v; sacc[0][2]+=a0*k2v; sacc[0][3]+=a0*k3v;
            sacc[1][0]+=a1*k0v; sacc[1][1]+=a1*k1v; sacc[1][2]+=a1*k2v; sacc[1][3]+=a1*k3v;
            sacc[2][0]+=a2*k0v; sacc[2][1]+=a2*k1v; sacc[2][2]+=a2*k2v; sacc[2][3]+=a2*k3v;
            sacc[3][0]+=a3*k0v; sacc[3][1]+=a3*k1v; sacc[3][2]+=a3*k2v; sacc[3][3]+=a3*k3v;
        }

        // online softmax (row groups = 16 consecutive lanes in a half-warp)
        #pragma unroll
        for (int i = 0; i < 4; i++) {
            float s0 = sacc[i][0]*scale, s1 = sacc[i][1]*scale;
            float s2 = sacc[i][2]*scale, s3 = sacc[i][3]*scale;
            float mx = fmaxf(fmaxf(s0, s1), fmaxf(s2, s3));
            #pragma unroll
            for (int o = 8; o > 0; o >>= 1) mx = fmaxf(mx, __shfl_xor_sync(0xffffffffu, mx, o));
            const float mn = fmaxf(m[i], mx);
            const float corr = __expf(m[i] - mn);
            const float p0 = __expf(s0 - mn), p1 = __expf(s1 - mn);
            const float p2 = __expf(s2 - mn), p3 = __expf(s3 - mn);
            float ps = p0 + p1 + p2 + p3;
            #pragma unroll
            for (int o = 8; o > 0; o >>= 1) ps += __shfl_xor_sync(0xffffffffu, ps, o);
            l[i] = l[i]*corr + ps;
            m[i] = mn;
            acc0[i] *= corr; acc1[i] *= corr;
            *(float4*)&Ps[r0 + i][c0] = make_float4(p0, p1, p2, p3);
        }
        __syncthreads();

        // O += P V  (each thread: 4 rows x 2 dims)
        #pragma unroll 8
        for (int n = 0; n < 64; n++) {
            const float v0 = Vs[n][d0], v1 = Vs[n][d0 + 1];
            #pragma unroll
            for (int i = 0; i < 4; i++) {
                const float p = Ps[r0 + i][n];
                acc0[i] += p * v0;
                acc1[i] += p * v1;
            }
        }
    }

    #pragma unroll
    for (int i = 0; i < 4; i++) {
        const float inv = 1.0f / l[i];
        const size_t orow = (size_t)(b*SEQ + qbase + r0 + i) * DMODEL + h*32;
        out[orow + d0]     = acc0[i] * inv;
        out[orow + d0 + 1] = acc1[i] * inv;
    }
}

// ---------------- launch ------------------------------------------------------
extern "C" void kernel_launch(void* const* d_in, const int* in_sizes, int n_in,
                              void* d_out, int out_size)
{
    const float* x     = (const float*)d_in[0];
    const float* Wq    = (const float*)d_in[1];
    const float* Wk    = (const float*)d_in[2];
    const float* Wv    = (const float*)d_in[3];
    const float* Wo    = (const float*)d_in[4];
    const float* ln1_g = (const float*)d_in[5];
    const float* ln1_b = (const float*)d_in[6];
    const float* ln2_g = (const float*)d_in[7];
    const float* ln2_b = (const float*)d_in[8];
    const float* W2    = (const float*)d_in[9];
    const float* b2    = (const float*)d_in[10];
    const float* W3    = (const float*)d_in[11];
    const float* b3    = (const float*)d_in[12];
    float* out = (float*)d_out;

    float *xn, *qkv, *attn, *mlpin, *yn, *hbuf;
    cudaGetSymbolAddress((void**)&xn,    g_xn);
    cudaGetSymbolAddress((void**)&qkv,   g_qkv);
    cudaGetSymbolAddress((void**)&attn,  g_attn);
    cudaGetSymbolAddress((void**)&mlpin, g_mlpin);
    cudaGetSymbolAddress((void**)&yn,    g_yn);
    cudaGetSymbolAddress((void**)&hbuf,  g_h);

    const dim3 gN256(2, NROW/128);    // N=256
    const dim3 gN1024(8, NROW/128);   // N=1024

    // LN1
    ln_kernel<<<NROW, 256>>>(x, ln1_g, ln1_b, xn);

    // QKV projections (RoPE fused into Q,K epilogues)
    gemm_nt<EPI_ROPE><<<gN256, 256>>>(xn, DMODEL, Wq, DMODEL, qkv + 0,   768, DMODEL, nullptr, nullptr, 0);
    gemm_nt<EPI_ROPE><<<gN256, 256>>>(xn, DMODEL, Wk, DMODEL, qkv + 256, 768, DMODEL, nullptr, nullptr, 0);
    gemm_nt<EPI_NONE><<<gN256, 256>>>(xn, DMODEL, Wv, DMODEL, qkv + 512, 768, DMODEL, nullptr, nullptr, 0);

    // attention
    flash_attn<<<dim3(SEQ/64, BATCH*NHEAD), 256>>>(qkv, attn);

    // output projection + residual -> mlp_in
    gemm_nt<EPI_RESID><<<gN256, 256>>>(attn, DMODEL, Wo, DMODEL, mlpin, DMODEL, DMODEL, nullptr, x, DMODEL);

    // LN2
    ln_kernel<<<NROW, 256>>>(mlpin, ln2_g, ln2_b, yn);

    // MLP
    gemm_nt<EPI_BIAS_GELU><<<gN1024, 256>>>(yn, DMODEL, W2, DMODEL, hbuf, DMLP, DMODEL, b2, nullptr, 0);
    gemm_nt<EPI_BIAS_RESID><<<gN256, 256>>>(hbuf, DMLP, W3, DMLP, out, DMODEL, DMLP, b3, mlpin, DMODEL);
}

// round 5
// speedup vs baseline: 3.3580x; 3.3580x over previous
#include <cuda_runtime.h>
#include <math.h>
#include <stdint.h>

#define BATCH 2
#define SEQ   4096
#define DMODEL 256
#define NHEAD 8
#define DHEAD 32
#define DMLP  1024
#define NROW  (BATCH*SEQ)   // 8192

// ---------------- scratch (static device globals; no allocation) -------------
__device__ float g_xn[NROW*DMODEL];
__device__ float g_qkv[NROW*3*DMODEL];
__device__ float g_attn[NROW*DMODEL];
__device__ float g_mlpin[NROW*DMODEL];
__device__ float g_yn[NROW*DMODEL];
__device__ float g_h[NROW*DMLP];

// inv_freq[i] = 10000^(-i/16) = 10^(-i/4)
__constant__ float c_invfreq[16] = {
    1.0f, 0.5623413251903491f, 0.31622776601683794f, 0.17782794100389228f,
    0.1f, 0.05623413251903491f, 0.031622776601683794f, 0.017782794100389228f,
    0.01f, 0.005623413251903491f, 0.0031622776601683794f, 0.0017782794100389228f,
    0.001f, 0.0005623413251903491f, 0.00031622776601683794f, 0.00017782794100389227f
};

// tf32 round-to-nearest (unbiased; value remains a valid fp32)
__device__ __forceinline__ float f2tf(float x) {
    uint32_t u;
    asm("cvt.rna.tf32.f32 %0, %1;" : "=r"(u) : "f"(x));
    return __uint_as_float(u);
}

// D += A*B, m16n8k8 tf32
__device__ __forceinline__ void mma_tf32(float* d, const uint32_t* a, uint32_t b0, uint32_t b1) {
    asm volatile("mma.sync.aligned.m16n8k8.row.col.f32.tf32.tf32.f32 "
        "{%0,%1,%2,%3}, {%4,%5,%6,%7}, {%8,%9}, {%0,%1,%2,%3};\n"
        : "+f"(d[0]), "+f"(d[1]), "+f"(d[2]), "+f"(d[3])
        : "r"(a[0]), "r"(a[1]), "r"(a[2]), "r"(a[3]), "r"(b0), "r"(b1));
}

// ---------------- LayerNorm: one block per row, 256 threads ------------------
__global__ void ln_kernel(const float* __restrict__ x, const float* __restrict__ g,
                          const float* __restrict__ b, float* __restrict__ out)
{
    const int row = blockIdx.x;
    const int t   = threadIdx.x;
    const float v = x[row*DMODEL + t];
    __shared__ float red1[8];
    __shared__ float red2[8];

    float s = v;
    #pragma unroll
    for (int o = 16; o > 0; o >>= 1) s += __shfl_xor_sync(0xffffffffu, s, o);
    if ((t & 31) == 0) red1[t >> 5] = s;
    __syncthreads();
    float mean = 0.f;
    #pragma unroll
    for (int i = 0; i < 8; i++) mean += red1[i];
    mean *= (1.0f/DMODEL);
    const float d = v - mean;

    float s2 = d*d;
    #pragma unroll
    for (int o = 16; o > 0; o >>= 1) s2 += __shfl_xor_sync(0xffffffffu, s2, o);
    if ((t & 31) == 0) red2[t >> 5] = s2;
    __syncthreads();
    float var = 0.f;
    #pragma unroll
    for (int i = 0; i < 8; i++) var += red2[i];
    var *= (1.0f/DMODEL);

    out[row*DMODEL + t] = d * rsqrtf(var + 1e-5f) * g[t] + b[t];
}

// ---------------- GEMM (C = A * B^T) via tf32 mma ----------------------------
// A: [M,K] row-major, B: [N,K] row-major, C: [M,N]
// Block 128x128x32; 8 warps as 2(m) x 4(n); warp tile 64x32; m16n8k8.
enum { EPI_NONE=0, EPI_ROPE=1, EPI_BIAS_GELU=2, EPI_RESID=3, EPI_BIAS_RESID=4 };

template<int EPI>
__global__ __launch_bounds__(256, 2)
void gemm_tf32(const float* __restrict__ A, int lda,
               const float* __restrict__ Bw, int ldb,
               float* __restrict__ C, int ldc,
               int K,
               const float* __restrict__ bias,
               const float* __restrict__ resid, int ldr)
{
    __shared__ float As[128][36];
    __shared__ float Bs[128][36];

    const int tid = threadIdx.x;
    const int w   = tid >> 5;
    const int L   = tid & 31;
    const int gid = L >> 2;     // 0..7
    const int t   = L & 3;      // 0..3
    const int wm  = w >> 2;     // 0..1
    const int wn  = w & 3;      // 0..3
    const int m0  = blockIdx.y * 128;
    const int n0  = blockIdx.x * 128;

    const int lrow = tid >> 1;          // 0..127
    const int lk   = (tid & 1) * 16;    // 0 or 16

    float acc[4][4][4];
    #pragma unroll
    for (int i = 0; i < 4; i++)
        #pragma unroll
        for (int j = 0; j < 4; j++)
            #pragma unroll
            for (int r = 0; r < 4; r++) acc[i][j][r] = 0.f;

    const float* Ap = A  + (size_t)(m0 + lrow) * lda + lk;
    const float* Bp = Bw + (size_t)(n0 + lrow) * ldb + lk;

    for (int k0 = 0; k0 < K; k0 += 32) {
        float4 a0 = *(const float4*)(Ap + k0);
        float4 a1 = *(const float4*)(Ap + k0 + 4);
        float4 a2 = *(const float4*)(Ap + k0 + 8);
        float4 a3 = *(const float4*)(Ap + k0 + 12);
        float4 b0 = *(const float4*)(Bp + k0);
        float4 b1 = *(const float4*)(Bp + k0 + 4);
        float4 b2 = *(const float4*)(Bp + k0 + 8);
        float4 b3 = *(const float4*)(Bp + k0 + 12);
        __syncthreads();
        {
            float av[16] = {a0.x,a0.y,a0.z,a0.w, a1.x,a1.y,a1.z,a1.w,
                            a2.x,a2.y,a2.z,a2.w, a3.x,a3.y,a3.z,a3.w};
            float bv[16] = {b0.x,b0.y,b0.z,b0.w, b1.x,b1.y,b1.z,b1.w,
                            b2.x,b2.y,b2.z,b2.w, b3.x,b3.y,b3.z,b3.w};
            #pragma unroll
            for (int i = 0; i < 16; i++) {
                As[lrow][lk + i] = f2tf(av[i]);
                Bs[lrow][lk + i] = f2tf(bv[i]);
            }
        }
        __syncthreads();

        #pragma unroll
        for (int kb = 0; kb < 4; kb++) {
            uint32_t af[4][4];
            #pragma unroll
            for (int mi = 0; mi < 4; mi++) {
                const int r = wm*64 + mi*16 + gid;
                af[mi][0] = __float_as_uint(As[r    ][8*kb + t]);
                af[mi][1] = __float_as_uint(As[r + 8][8*kb + t]);
                af[mi][2] = __float_as_uint(As[r    ][8*kb + t + 4]);
                af[mi][3] = __float_as_uint(As[r + 8][8*kb + t + 4]);
            }
            #pragma unroll
            for (int nj = 0; nj < 4; nj++) {
                const int c = wn*32 + nj*8 + gid;
                const uint32_t bf0 = __float_as_uint(Bs[c][8*kb + t]);
                const uint32_t bf1 = __float_as_uint(Bs[c][8*kb + t + 4]);
                #pragma unroll
                for (int mi = 0; mi < 4; mi++)
                    mma_tf32(acc[mi][nj], af[mi], bf0, bf1);
            }
        }
    }

    // epilogue: each (mi,nj) frag: rows gid, gid+8; cols 2t,2t+1
    #pragma unroll
    for (int mi = 0; mi < 4; mi++) {
        #pragma unroll
        for (int half = 0; half < 2; half++) {
            const int gm = m0 + wm*64 + mi*16 + gid + half*8;
            #pragma unroll
            for (int nj = 0; nj < 4; nj++) {
                const int gc = n0 + wn*32 + nj*8 + 2*t;   // even
                float v0 = acc[mi][nj][half*2 + 0];
                float v1 = acc[mi][nj][half*2 + 1];

                if (EPI == EPI_ROPE) {
                    const int s  = gm & (SEQ - 1);
                    const int dd = gc & (DHEAD - 1);      // even
                    const float ang = (float)s * c_invfreq[dd >> 1];
                    float sn, cs;
                    sincosf(ang, &sn, &cs);
                    const float e = v0, o = v1;
                    v0 = e*cs - o*sn;
                    v1 = o*cs + e*sn;
                } else if (EPI == EPI_BIAS_GELU) {
                    float t0 = v0 + bias[gc], t1 = v1 + bias[gc + 1];
                    v0 = 0.5f * t0 * (1.0f + erff(t0 * 0.7071067811865476f));
                    v1 = 0.5f * t1 * (1.0f + erff(t1 * 0.7071067811865476f));
                } else if (EPI == EPI_RESID) {
                    v0 += resid[(size_t)gm * ldr + gc];
                    v1 += resid[(size_t)gm * ldr + gc + 1];
                } else if (EPI == EPI_BIAS_RESID) {
                    v0 += bias[gc]     + resid[(size_t)gm * ldr + gc];
                    v1 += bias[gc + 1] + resid[(size_t)gm * ldr + gc + 1];
                }
                *(float2*)&C[(size_t)gm * ldc + gc] = make_float2(v0, v1);
            }
        }
    }
}

// ---------------- Flash attention via tf32 mma -------------------------------
// CTA: 64 q-rows, 4 warps (warp = 16 q-rows x 64 k-cols). K-tile = 64.
__global__ __launch_bounds__(128)
void flash_attn_mma(const float* __restrict__ qkv, float* __restrict__ out)
{
    __shared__ float Qs[64][36];
    __shared__ float Ks[64][36];
    __shared__ float Vt[32][68];
    __shared__ float Ps[4][16][68];

    const int tid = threadIdx.x;
    const int w   = tid >> 5;
    const int L   = tid & 31;
    const int gid = L >> 2;
    const int t   = L & 3;
    const int b   = blockIdx.y >> 3;
    const int h   = blockIdx.y & 7;
    const int qbase = blockIdx.x * 64;
    const int qw  = w * 16;

    // load Q tile (tf32-rounded)
    for (int e = tid; e < 64*32; e += 128) {
        const int r = e >> 5, d = e & 31;
        Qs[r][d] = f2tf(qkv[(size_t)(b*SEQ + qbase + r) * 768 + h*32 + d]);
    }
    __syncthreads();

    // hoist Q fragments (constant across k-tiles)
    uint32_t qa[4][4];
    #pragma unroll
    for (int kb = 0; kb < 4; kb++) {
        qa[kb][0] = __float_as_uint(Qs[qw + gid    ][8*kb + t]);
        qa[kb][1] = __float_as_uint(Qs[qw + gid + 8][8*kb + t]);
        qa[kb][2] = __float_as_uint(Qs[qw + gid    ][8*kb + t + 4]);
        qa[kb][3] = __float_as_uint(Qs[qw + gid + 8][8*kb + t + 4]);
    }

    float oacc[4][4];
    #pragma unroll
    for (int j = 0; j < 4; j++)
        #pragma unroll
        for (int r = 0; r < 4; r++) oacc[j][r] = 0.f;
    float mA = -1e30f, mB = -1e30f, lA = 0.f, lB = 0.f;
    const float scale = 0.17677669529663687f;  // 1/sqrt(32)

    for (int kt = 0; kt < SEQ/64; kt++) {
        __syncthreads();
        const size_t base = (size_t)(b*SEQ + kt*64) * 768 + h*32;
        // K tile
        for (int e = tid; e < 64*32; e += 128) {
            const int r = e >> 5, d = e & 31;
            Ks[r][d] = f2tf(qkv[base + (size_t)r*768 + 256 + d]);
        }
        // V tile, transposed into Vt[dim][kpos]
        {
            const int kp = tid & 63;
            const int dh = (tid >> 6) * 16;
            const float* vsrc = qkv + base + (size_t)kp*768 + 512 + dh;
            float4 v0 = *(const float4*)(vsrc);
            float4 v1 = *(const float4*)(vsrc + 4);
            float4 v2 = *(const float4*)(vsrc + 8);
            float4 v3 = *(const float4*)(vsrc + 12);
            float vv[16] = {v0.x,v0.y,v0.z,v0.w, v1.x,v1.y,v1.z,v1.w,
                            v2.x,v2.y,v2.z,v2.w, v3.x,v3.y,v3.z,v3.w};
            #pragma unroll
            for (int i = 0; i < 16; i++) Vt[dh + i][kp] = f2tf(vv[i]);
        }
        __syncthreads();

        // S = Q K^T : 8 n-frags x 4 k-steps
        float sa[8][4];
        #pragma unroll
        for (int j = 0; j < 8; j++)
            #pragma unroll
            for (int r = 0; r < 4; r++) sa[j][r] = 0.f;

        #pragma unroll
        for (int kb = 0; kb < 4; kb++) {
            #pragma unroll
            for (int j = 0; j < 8; j++) {
                const int kc = 8*j + gid;
                const uint32_t b0 = __float_as_uint(Ks[kc][8*kb + t]);
                const uint32_t b1 = __float_as_uint(Ks[kc][8*kb + t + 4]);
                mma_tf32(sa[j], qa[kb], b0, b1);
            }
        }

        // scale
        #pragma unroll
        for (int j = 0; j < 8; j++)
            #pragma unroll
            for (int r = 0; r < 4; r++) sa[j][r] *= scale;

        // row max (rows gid [A] and gid+8 [B]); reduce over 4-lane groups
        float mxA = -1e30f, mxB = -1e30f;
        #pragma unroll
        for (int j = 0; j < 8; j++) {
            mxA = fmaxf(mxA, fmaxf(sa[j][0], sa[j][1]));
            mxB = fmaxf(mxB, fmaxf(sa[j][2], sa[j][3]));
        }
        #pragma unroll
        for (int o = 1; o <= 2; o <<= 1) {
            mxA = fmaxf(mxA, __shfl_xor_sync(0xffffffffu, mxA, o));
            mxB = fmaxf(mxB, __shfl_xor_sync(0xffffffffu, mxB, o));
        }
        const float mnA = fmaxf(mA, mxA);
        const float mnB = fmaxf(mB, mxB);
        const float corrA = __expf(mA - mnA);
        const float corrB = __expf(mB - mnB);
        mA = mnA; mB = mnB;

        float psumA = 0.f, psumB = 0.f;
        #pragma unroll
        for (int j = 0; j < 8; j++) {
            const float p0 = __expf(sa[j][0] - mA);
            const float p1 = __expf(sa[j][1] - mA);
            const float p2 = __expf(sa[j][2] - mB);
            const float p3 = __expf(sa[j][3] - mB);
            psumA += p0 + p1;
            psumB += p2 + p3;
            Ps[w][gid    ][8*j + 2*t]     = f2tf(p0);
            Ps[w][gid    ][8*j + 2*t + 1] = f2tf(p1);
            Ps[w][gid + 8][8*j + 2*t]     = f2tf(p2);
            Ps[w][gid + 8][8*j + 2*t + 1] = f2tf(p3);
        }
        lA = lA * corrA + psumA;
        lB = lB * corrB + psumB;
        #pragma unroll
        for (int j = 0; j < 4; j++) {
            oacc[j][0] *= corrA; oacc[j][1] *= corrA;
            oacc[j][2] *= corrB; oacc[j][3] *= corrB;
        }
        __syncwarp();

        // O += P V : 8 k-steps x 4 n-frags
        #pragma unroll
        for (int ks = 0; ks < 8; ks++) {
            uint32_t af[4];
            af[0] = __float_as_uint(Ps[w][gid    ][8*ks + t]);
            af[1] = __float_as_uint(Ps[w][gid + 8][8*ks + t]);
            af[2] = __float_as_uint(Ps[w][gid    ][8*ks + t + 4]);
            af[3] = __float_as_uint(Ps[w][gid + 8][8*ks + t + 4]);
            #pragma unroll
            for (int j = 0; j < 4; j++) {
                const int dv = 8*j + gid;
                const uint32_t b0 = __float_as_uint(Vt[dv][8*ks + t]);
                const uint32_t b1 = __float_as_uint(Vt[dv][8*ks + t + 4]);
                mma_tf32(oacc[j], af, b0, b1);
            }
        }
        // (next softmax write to Ps is ordered behind the loop-top __syncthreads)
    }

    // finalize l over 4-lane groups
    #pragma unroll
    for (int o = 1; o <= 2; o <<= 1) {
        lA += __shfl_xor_sync(0xffffffffu, lA, o);
        lB += __shfl_xor_sync(0xffffffffu, lB, o);
    }
    const float invA = 1.0f / lA;
    const float invB = 1.0f / lB;

    #pragma unroll
    for (int j = 0; j < 4; j++) {
        const int gc = h*32 + 8*j + 2*t;
        const int rA = b*SEQ + qbase + qw + gid;
        const int rB = rA + 8;
        *(float2*)&out[(size_t)rA * DMODEL + gc] = make_float2(oacc[j][0]*invA, oacc[j][1]*invA);
        *(float2*)&out[(size_t)rB * DMODEL + gc] = make_float2(oacc[j][2]*invB, oacc[j][3]*invB);
    }
}

// ---------------- launch ------------------------------------------------------
extern "C" void kernel_launch(void* const* d_in, const int* in_sizes, int n_in,
                              void* d_out, int out_size)
{
    const float* x     = (const float*)d_in[0];
    const float* Wq    = (const float*)d_in[1];
    const float* Wk    = (const float*)d_in[2];
    const float* Wv    = (const float*)d_in[3];
    const float* Wo    = (const float*)d_in[4];
    const float* ln1_g = (const float*)d_in[5];
    const float* ln1_b = (const float*)d_in[6];
    const float* ln2_g = (const float*)d_in[7];
    const float* ln2_b = (const float*)d_in[8];
    const float* W2    = (const float*)d_in[9];
    const float* b2    = (const float*)d_in[10];
    const float* W3    = (const float*)d_in[11];
    const float* b3    = (const float*)d_in[12];
    float* out = (float*)d_out;

    float *xn, *qkv, *attn, *mlpin, *yn, *hbuf;
    cudaGetSymbolAddress((void**)&xn,    g_xn);
    cudaGetSymbolAddress((void**)&qkv,   g_qkv);
    cudaGetSymbolAddress((void**)&attn,  g_attn);
    cudaGetSymbolAddress((void**)&mlpin, g_mlpin);
    cudaGetSymbolAddress((void**)&yn,    g_yn);
    cudaGetSymbolAddress((void**)&hbuf,  g_h);

    const dim3 gN256(2, NROW/128);    // N=256
    const dim3 gN1024(8, NROW/128);   // N=1024

    // LN1
    ln_kernel<<<NROW, 256>>>(x, ln1_g, ln1_b, xn);

    // QKV projections (RoPE fused into Q,K epilogues)
    gemm_tf32<EPI_ROPE><<<gN256, 256>>>(xn, DMODEL, Wq, DMODEL, qkv + 0,   768, DMODEL, nullptr, nullptr, 0);
    gemm_tf32<EPI_ROPE><<<gN256, 256>>>(xn, DMODEL, Wk, DMODEL, qkv + 256, 768, DMODEL, nullptr, nullptr, 0);
    gemm_tf32<EPI_NONE><<<gN256, 256>>>(xn, DMODEL, Wv, DMODEL, qkv + 512, 768, DMODEL, nullptr, nullptr, 0);

    // attention
    flash_attn_mma<<<dim3(SEQ/64, BATCH*NHEAD), 128>>>(qkv, attn);

    // output projection + residual -> mlp_in
    gemm_tf32<EPI_RESID><<<gN256, 256>>>(attn, DMODEL, Wo, DMODEL, mlpin, DMODEL, DMODEL, nullptr, x, DMODEL);

    // LN2
    ln_kernel<<<NROW, 256>>>(mlpin, ln2_g, ln2_b, yn);

    // MLP
    gemm_tf32<EPI_BIAS_GELU><<<gN1024, 256>>>(yn, DMODEL, W2, DMODEL, hbuf, DMLP, DMODEL, b2, nullptr, 0);
    gemm_tf32<EPI_BIAS_RESID><<<gN256, 256>>>(hbuf, DMLP, W3, DMLP, out, DMODEL, DMLP, b3, mlpin, DMODEL);
}

// round 6
// speedup vs baseline: 4.6022x; 1.3705x over previous
#include <cuda_runtime.h>
#include <math.h>
#include <stdint.h>

#define BATCH 2
#define SEQ   4096
#define DMODEL 256
#define NHEAD 8
#define DHEAD 32
#define DMLP  1024
#define NROW  (BATCH*SEQ)   // 8192

// ---------------- scratch (static device globals; no allocation) -------------
__device__ float g_xn[NROW*DMODEL];
__device__ float g_qkv[NROW*3*DMODEL];
__device__ float g_attn[NROW*DMODEL];
__device__ float g_mlpin[NROW*DMODEL];
__device__ float g_yn[NROW*DMODEL];
__device__ float g_h[NROW*DMLP];

// inv_freq[i] = 10000^(-i/16) = 10^(-i/4)
__constant__ float c_invfreq[16] = {
    1.0f, 0.5623413251903491f, 0.31622776601683794f, 0.17782794100389228f,
    0.1f, 0.05623413251903491f, 0.031622776601683794f, 0.017782794100389228f,
    0.01f, 0.005623413251903491f, 0.0031622776601683794f, 0.0017782794100389228f,
    0.001f, 0.0005623413251903491f, 0.00031622776601683794f, 0.00017782794100389227f
};

__device__ __forceinline__ void cp16(float* smem_dst, const float* gmem_src) {
    uint32_t s = (uint32_t)__cvta_generic_to_shared(smem_dst);
    asm volatile("cp.async.cg.shared.global [%0], [%1], 16;" :: "r"(s), "l"(gmem_src));
}
#define CP_COMMIT() asm volatile("cp.async.commit_group;")
#define CP_WAIT0()  asm volatile("cp.async.wait_group 0;")

// D += A*B, m16n8k8 tf32 (HW truncates fp32 operands to tf32)
__device__ __forceinline__ void mma_tf32(float* d, const uint32_t* a, uint32_t b0, uint32_t b1) {
    asm volatile("mma.sync.aligned.m16n8k8.row.col.f32.tf32.tf32.f32 "
        "{%0,%1,%2,%3}, {%4,%5,%6,%7}, {%8,%9}, {%0,%1,%2,%3};\n"
        : "+f"(d[0]), "+f"(d[1]), "+f"(d[2]), "+f"(d[3])
        : "r"(a[0]), "r"(a[1]), "r"(a[2]), "r"(a[3]), "r"(b0), "r"(b1));
}

// ---------------- LayerNorm: one block per row, 256 threads ------------------
__global__ void ln_kernel(const float* __restrict__ x, const float* __restrict__ g,
                          const float* __restrict__ b, float* __restrict__ out)
{
    const int row = blockIdx.x;
    const int t   = threadIdx.x;
    const float v = x[row*DMODEL + t];
    __shared__ float red1[8];
    __shared__ float red2[8];

    float s = v;
    #pragma unroll
    for (int o = 16; o > 0; o >>= 1) s += __shfl_xor_sync(0xffffffffu, s, o);
    if ((t & 31) == 0) red1[t >> 5] = s;
    __syncthreads();
    float mean = 0.f;
    #pragma unroll
    for (int i = 0; i < 8; i++) mean += red1[i];
    mean *= (1.0f/DMODEL);
    const float d = v - mean;

    float s2 = d*d;
    #pragma unroll
    for (int o = 16; o > 0; o >>= 1) s2 += __shfl_xor_sync(0xffffffffu, s2, o);
    if ((t & 31) == 0) red2[t >> 5] = s2;
    __syncthreads();
    float var = 0.f;
    #pragma unroll
    for (int i = 0; i < 8; i++) var += red2[i];
    var *= (1.0f/DMODEL);

    out[row*DMODEL + t] = d * rsqrtf(var + 1e-5f) * g[t] + b[t];
}

// ---------------- GEMM (C = A * B^T) via tf32 mma, cp.async 2-stage ----------
// A: [M,K] row-major, B: [N,K] row-major, C: [M,N]
// Tile BMx128x32, BM=32*MI; 8 warps as 2(m)x4(n); warp tile (16*MI)x32.
// EPI_QKV: Bw=Wq, bias=Wk, resid=Wv; blockIdx.x in 0..5 selects weight;
//          rope applied to output cols < 512.
enum { EPI_NONE=0, EPI_ROPE=1, EPI_BIAS_GELU=2, EPI_RESID=3, EPI_BIAS_RESID=4, EPI_QKV=5 };

template<int MI, int EPI>
__global__ __launch_bounds__(256, 2)
void gemm_v2(const float* __restrict__ A, int lda,
             const float* __restrict__ Bw, int ldb,
             float* __restrict__ C, int ldc, int K,
             const float* __restrict__ bias,
             const float* __restrict__ resid, int ldr)
{
    constexpr int BM = 32*MI;
    extern __shared__ float sm[];
    float (*As)[36] = (float(*)[36])sm;                 // [2*BM][36]
    float (*Bs)[36] = (float(*)[36])(sm + 2*BM*36);     // [2*128][36]

    const int tid = threadIdx.x;
    const int w = tid>>5, L = tid&31, gid = L>>2, t = L&3;
    const int wm = w>>2, wn = w&3;
    const int m0 = blockIdx.y * BM;
    const int bx = blockIdx.x;

    const float* Bmat;
    int nlocal0, ncout0;
    if (EPI == EPI_QKV) {
        Bmat = (bx < 2) ? Bw : (bx < 4) ? bias : resid;
        nlocal0 = (bx & 1) * 128;
        ncout0  = bx * 128;
    } else {
        Bmat = Bw;
        nlocal0 = bx * 128;
        ncout0  = nlocal0;
    }

    float acc[MI][4][4];
    #pragma unroll
    for (int i = 0; i < MI; i++)
        #pragma unroll
        for (int j = 0; j < 4; j++)
            #pragma unroll
            for (int r = 0; r < 4; r++) acc[i][j][r] = 0.f;

    constexpr int ACH = BM/32;   // 16B chunks per thread for A tile

    // stage loaders
    auto loadA = [&](int stg, int k0) {
        #pragma unroll
        for (int c = 0; c < ACH; c++) {
            const int ci = tid*ACH + c;
            const int r = ci>>3, cc = (ci&7)*4;
            cp16(&As[stg*BM + r][cc], A + (size_t)(m0+r)*lda + k0 + cc);
        }
    };
    auto loadB = [&](int stg, int k0) {
        #pragma unroll
        for (int c = 0; c < 4; c++) {
            const int ci = tid*4 + c;
            const int r = ci>>3, cc = (ci&7)*4;
            cp16(&Bs[stg*128 + r][cc], Bmat + (size_t)(nlocal0+r)*ldb + k0 + cc);
        }
    };

    loadA(0, 0); loadB(0, 0); CP_COMMIT();

    const int iters = K/32;
    for (int it = 0; it < iters; it++) {
        CP_WAIT0();
        __syncthreads();
        if (it + 1 < iters) { loadA((it+1)&1, (it+1)*32); loadB((it+1)&1, (it+1)*32); CP_COMMIT(); }

        const float (*Ac)[36] = (const float(*)[36])(As + (it&1)*BM);
        const float (*Bc)[36] = (const float(*)[36])(Bs + (it&1)*128);

        #pragma unroll
        for (int kb = 0; kb < 4; kb++) {
            uint32_t af[MI][4];
            #pragma unroll
            for (int mi = 0; mi < MI; mi++) {
                const int r = wm*(16*MI) + mi*16 + gid;
                af[mi][0] = __float_as_uint(Ac[r    ][8*kb + t]);
                af[mi][1] = __float_as_uint(Ac[r + 8][8*kb + t]);
                af[mi][2] = __float_as_uint(Ac[r    ][8*kb + t + 4]);
                af[mi][3] = __float_as_uint(Ac[r + 8][8*kb + t + 4]);
            }
            #pragma unroll
            for (int nj = 0; nj < 4; nj++) {
                const int cix = wn*32 + nj*8 + gid;
                const uint32_t b0 = __float_as_uint(Bc[cix][8*kb + t]);
                const uint32_t b1 = __float_as_uint(Bc[cix][8*kb + t + 4]);
                #pragma unroll
                for (int mi = 0; mi < MI; mi++)
                    mma_tf32(acc[mi][nj], af[mi], b0, b1);
            }
        }
    }

    // epilogue
    #pragma unroll
    for (int mi = 0; mi < MI; mi++) {
        #pragma unroll
        for (int half = 0; half < 2; half++) {
            const int gm = m0 + wm*(16*MI) + mi*16 + gid + half*8;
            #pragma unroll
            for (int nj = 0; nj < 4; nj++) {
                const int gc = ncout0 + wn*32 + nj*8 + 2*t;   // even
                float v0 = acc[mi][nj][half*2 + 0];
                float v1 = acc[mi][nj][half*2 + 1];

                if (EPI == EPI_QKV) {
                    if (gc < 512) {   // rope on Q and K outputs
                        const int s  = gm & (SEQ - 1);
                        const int dd = gc & (DHEAD - 1);
                        const float ang = (float)s * c_invfreq[dd >> 1];
                        float sn, cs;
                        sincosf(ang, &sn, &cs);
                        const float e = v0, o = v1;
                        v0 = e*cs - o*sn;
                        v1 = o*cs + e*sn;
                    }
                } else if (EPI == EPI_ROPE) {
                    const int s  = gm & (SEQ - 1);
                    const int dd = gc & (DHEAD - 1);
                    const float ang = (float)s * c_invfreq[dd >> 1];
                    float sn, cs;
                    sincosf(ang, &sn, &cs);
                    const float e = v0, o = v1;
                    v0 = e*cs - o*sn;
                    v1 = o*cs + e*sn;
                } else if (EPI == EPI_BIAS_GELU) {
                    float t0 = v0 + bias[gc], t1 = v1 + bias[gc + 1];
                    v0 = 0.5f * t0 * (1.0f + erff(t0 * 0.7071067811865476f));
                    v1 = 0.5f * t1 * (1.0f + erff(t1 * 0.7071067811865476f));
                } else if (EPI == EPI_RESID) {
                    v0 += resid[(size_t)gm * ldr + gc];
                    v1 += resid[(size_t)gm * ldr + gc + 1];
                } else if (EPI == EPI_BIAS_RESID) {
                    v0 += bias[gc]     + resid[(size_t)gm * ldr + gc];
                    v1 += bias[gc + 1] + resid[(size_t)gm * ldr + gc + 1];
                }
                *(float2*)&C[(size_t)gm * ldc + gc] = make_float2(v0, v1);
            }
        }
    }
}

// ---------------- Flash attention, tf32 mma, cp.async double-buffered --------
// CTA: 128 q-rows, 8 warps (each warp 16 q-rows x 64 k-cols). K-tile = 64.
__global__ __launch_bounds__(256, 2)
void flash_attn_v2(const float* __restrict__ qkv, float* __restrict__ out)
{
    extern __shared__ float sm[];
    float (*Qs)[36] = (float(*)[36])sm;                                 // [128][36]
    float (*Ks)[36] = (float(*)[36])(sm + 128*36);                      // [2*64][36]
    float (*Vs)[40] = (float(*)[40])(sm + 128*36 + 2*64*36);            // [2*64][40]
    float (*PsA)[68] = (float(*)[68])(sm + 128*36 + 2*64*36 + 2*64*40); // [8*16][68]

    const int tid = threadIdx.x;
    const int w = tid>>5, L = tid&31, gid = L>>2, t = L&3;
    const int b = blockIdx.y >> 3, h = blockIdx.y & 7;
    const int qbase = blockIdx.x * 128;
    const int qw = w * 16;
    float (*Pw)[68] = PsA + w*16;

    const size_t qoff  = (size_t)(b*SEQ + qbase) * 768 + h*32;
    const size_t kvoff = (size_t)(b*SEQ) * 768 + h*32;

    // prologue: Q (4 chunks/thread) + K0/V0 (2 chunks each)
    #pragma unroll
    for (int c = 0; c < 4; c++) {
        const int ci = tid*4 + c;
        const int r = ci>>3, cc = (ci&7)*4;
        cp16(&Qs[r][cc], qkv + qoff + (size_t)r*768 + cc);
    }
    auto loadKV = [&](int stg, int kt) {
        #pragma unroll
        for (int c = 0; c < 2; c++) {
            const int ci = tid*2 + c;
            const int r = ci>>3, cc = (ci&7)*4;
            const float* src = qkv + kvoff + (size_t)(kt*64 + r)*768 + cc;
            cp16(&Ks[stg*64 + r][cc], src + 256);
            cp16(&Vs[stg*64 + r][cc], src + 512);
        }
    };
    loadKV(0, 0);
    CP_COMMIT();
    CP_WAIT0();
    __syncthreads();

    // hoist Q fragments (constant across k-tiles)
    uint32_t qa[4][4];
    #pragma unroll
    for (int kb = 0; kb < 4; kb++) {
        qa[kb][0] = __float_as_uint(Qs[qw + gid    ][8*kb + t]);
        qa[kb][1] = __float_as_uint(Qs[qw + gid + 8][8*kb + t]);
        qa[kb][2] = __float_as_uint(Qs[qw + gid    ][8*kb + t + 4]);
        qa[kb][3] = __float_as_uint(Qs[qw + gid + 8][8*kb + t + 4]);
    }

    float oacc[4][4];
    #pragma unroll
    for (int j = 0; j < 4; j++)
        #pragma unroll
        for (int r = 0; r < 4; r++) oacc[j][r] = 0.f;
    float mA = -1e30f, mB = -1e30f, lA = 0.f, lB = 0.f;
    const float scale = 0.17677669529663687f;  // 1/sqrt(32)

    for (int kt = 0; kt < SEQ/64; kt++) {
        if (kt > 0) { CP_WAIT0(); }
        __syncthreads();
        if (kt + 1 < SEQ/64) { loadKV((kt+1)&1, kt+1); CP_COMMIT(); }

        const float (*Kc)[36] = (const float(*)[36])(Ks + (kt&1)*64);
        const float (*Vc)[40] = (const float(*)[40])(Vs + (kt&1)*64);

        // S = Q K^T : 8 n-frags x 4 k-steps
        float sa[8][4];
        #pragma unroll
        for (int j = 0; j < 8; j++)
            #pragma unroll
            for (int r = 0; r < 4; r++) sa[j][r] = 0.f;

        #pragma unroll
        for (int kb = 0; kb < 4; kb++) {
            #pragma unroll
            for (int j = 0; j < 8; j++) {
                const int kc = 8*j + gid;
                const uint32_t b0 = __float_as_uint(Kc[kc][8*kb + t]);
                const uint32_t b1 = __float_as_uint(Kc[kc][8*kb + t + 4]);
                mma_tf32(sa[j], qa[kb], b0, b1);
            }
        }

        #pragma unroll
        for (int j = 0; j < 8; j++)
            #pragma unroll
            for (int r = 0; r < 4; r++) sa[j][r] *= scale;

        // online softmax (rows gid [A], gid+8 [B]); reduce over 4-lane groups
        float mxA = -1e30f, mxB = -1e30f;
        #pragma unroll
        for (int j = 0; j < 8; j++) {
            mxA = fmaxf(mxA, fmaxf(sa[j][0], sa[j][1]));
            mxB = fmaxf(mxB, fmaxf(sa[j][2], sa[j][3]));
        }
        #pragma unroll
        for (int o = 1; o <= 2; o <<= 1) {
            mxA = fmaxf(mxA, __shfl_xor_sync(0xffffffffu, mxA, o));
            mxB = fmaxf(mxB, __shfl_xor_sync(0xffffffffu, mxB, o));
        }
        const float mnA = fmaxf(mA, mxA);
        const float mnB = fmaxf(mB, mxB);
        const float corrA = __expf(mA - mnA);
        const float corrB = __expf(mB - mnB);
        mA = mnA; mB = mnB;

        float psumA = 0.f, psumB = 0.f;
        #pragma unroll
        for (int j = 0; j < 8; j++) {
            const float p0 = __expf(sa[j][0] - mA);
            const float p1 = __expf(sa[j][1] - mA);
            const float p2 = __expf(sa[j][2] - mB);
            const float p3 = __expf(sa[j][3] - mB);
            psumA += p0 + p1;
            psumB += p2 + p3;
            Pw[gid    ][8*j + 2*t]     = p0;
            Pw[gid    ][8*j + 2*t + 1] = p1;
            Pw[gid + 8][8*j + 2*t]     = p2;
            Pw[gid + 8][8*j + 2*t + 1] = p3;
        }
        lA = lA * corrA + psumA;
        lB = lB * corrB + psumB;
        #pragma unroll
        for (int j = 0; j < 4; j++) {
            oacc[j][0] *= corrA; oacc[j][1] *= corrA;
            oacc[j][2] *= corrB; oacc[j][3] *= corrB;
        }
        __syncwarp();

        // O += P V : 8 k-steps x 4 n-frags; V natural layout (b = V[k][d])
        #pragma unroll
        for (int ks = 0; ks < 8; ks++) {
            uint32_t af[4];
            af[0] = __float_as_uint(Pw[gid    ][8*ks + t]);
            af[1] = __float_as_uint(Pw[gid + 8][8*ks + t]);
            af[2] = __float_as_uint(Pw[gid    ][8*ks + t + 4]);
            af[3] = __float_as_uint(Pw[gid + 8][8*ks + t + 4]);
            #pragma unroll
            for (int j = 0; j < 4; j++) {
                const int dv = 8*j + gid;
                const uint32_t b0 = __float_as_uint(Vc[8*ks + t    ][dv]);
                const uint32_t b1 = __float_as_uint(Vc[8*ks + t + 4][dv]);
                mma_tf32(oacc[j], af, b0, b1);
            }
        }
        // next iteration's Ps writes are same-warp; K/V overwrite guarded by top sync
    }

    #pragma unroll
    for (int o = 1; o <= 2; o <<= 1) {
        lA += __shfl_xor_sync(0xffffffffu, lA, o);
        lB += __shfl_xor_sync(0xffffffffu, lB, o);
    }
    const float invA = 1.0f / lA;
    const float invB = 1.0f / lB;

    #pragma unroll
    for (int j = 0; j < 4; j++) {
        const int gc = h*32 + 8*j + 2*t;
        const int rA = b*SEQ + qbase + qw + gid;
        const int rB = rA + 8;
        *(float2*)&out[(size_t)rA * DMODEL + gc] = make_float2(oacc[j][0]*invA, oacc[j][1]*invA);
        *(float2*)&out[(size_t)rB * DMODEL + gc] = make_float2(oacc[j][2]*invB, oacc[j][3]*invB);
    }
}

// ---------------- launch ------------------------------------------------------
extern "C" void kernel_launch(void* const* d_in, const int* in_sizes, int n_in,
                              void* d_out, int out_size)
{
    const float* x     = (const float*)d_in[0];
    const float* Wq    = (const float*)d_in[1];
    const float* Wk    = (const float*)d_in[2];
    const float* Wv    = (const float*)d_in[3];
    const float* Wo    = (const float*)d_in[4];
    const float* ln1_g = (const float*)d_in[5];
    const float* ln1_b = (const float*)d_in[6];
    const float* ln2_g = (const float*)d_in[7];
    const float* ln2_b = (const float*)d_in[8];
    const float* W2    = (const float*)d_in[9];
    const float* b2    = (const float*)d_in[10];
    const float* W3    = (const float*)d_in[11];
    const float* b3    = (const float*)d_in[12];
    float* out = (float*)d_out;

    float *xn, *qkv, *attn, *mlpin, *yn, *hbuf;
    cudaGetSymbolAddress((void**)&xn,    g_xn);
    cudaGetSymbolAddress((void**)&qkv,   g_qkv);
    cudaGetSymbolAddress((void**)&attn,  g_attn);
    cudaGetSymbolAddress((void**)&mlpin, g_mlpin);
    cudaGetSymbolAddress((void**)&yn,    g_yn);
    cudaGetSymbolAddress((void**)&hbuf,  g_h);

    const int smGemm128 = (2*128*36 + 2*128*36) * 4;   // 73728
    const int smGemm64  = (2*64*36  + 2*128*36) * 4;   // 55296
    const int smAttn    = (128*36 + 2*64*36 + 2*64*40 + 8*16*68) * 4;  // 92160

    cudaFuncSetAttribute(gemm_v2<4, EPI_QKV>,        cudaFuncAttributeMaxDynamicSharedMemorySize, smGemm128);
    cudaFuncSetAttribute(gemm_v2<4, EPI_BIAS_GELU>,  cudaFuncAttributeMaxDynamicSharedMemorySize, smGemm128);
    cudaFuncSetAttribute(gemm_v2<2, EPI_RESID>,      cudaFuncAttributeMaxDynamicSharedMemorySize, smGemm64);
    cudaFuncSetAttribute(gemm_v2<2, EPI_BIAS_RESID>, cudaFuncAttributeMaxDynamicSharedMemorySize, smGemm64);
    cudaFuncSetAttribute(flash_attn_v2,              cudaFuncAttributeMaxDynamicSharedMemorySize, smAttn);

    // LN1
    ln_kernel<<<NROW, 256>>>(x, ln1_g, ln1_b, xn);

    // Fused QKV projections (RoPE on Q,K cols) — one launch, 384 CTAs
    gemm_v2<4, EPI_QKV><<<dim3(6, NROW/128), 256, smGemm128>>>(
        xn, DMODEL, Wq, DMODEL, qkv, 768, DMODEL, Wk, Wv, 0);

    // attention
    flash_attn_v2<<<dim3(SEQ/128, BATCH*NHEAD), 256, smAttn>>>(qkv, attn);

    // output projection + residual -> mlp_in  (BM=64 -> 256 CTAs)
    gemm_v2<2, EPI_RESID><<<dim3(2, NROW/64), 256, smGemm64>>>(
        attn, DMODEL, Wo, DMODEL, mlpin, DMODEL, DMODEL, nullptr, x, DMODEL);

    // LN2
    ln_kernel<<<NROW, 256>>>(mlpin, ln2_g, ln2_b, yn);

    // MLP
    gemm_v2<4, EPI_BIAS_GELU><<<dim3(8, NROW/128), 256, smGemm128>>>(
        yn, DMODEL, W2, DMODEL, hbuf, DMLP, DMODEL, b2, nullptr, 0);
    gemm_v2<2, EPI_BIAS_RESID><<<dim3(2, NROW/64), 256, smGemm64>>>(
        hbuf, DMLP, W3, DMLP, out, DMODEL, DMLP, b3, mlpin, DMODEL);
}